// round 1
// baseline (speedup 1.0000x reference)
#include <cuda_runtime.h>
#include <cstdint>
#include <cstddef>

#define SEQ   256
#define BATCH 32
#define NVOC  10000
#define NH    256
#define NG    1024      // NH * 4 gates
#define MTOT  8192      // SEQ * BATCH

// ---------------- scratch (static device globals; no allocation) ----------------
__device__ float    g_gx[(size_t)MTOT * NG];     // gate inputs, reused by both layers (32 MB)
__device__ float    g_h1seq[(size_t)MTOT * NH];  // layer-0 hidden sequence
__device__ float    g_h2seq[(size_t)MTOT * NH];  // layer-1 hidden sequence
__device__ float    g_hbuf[2][BATCH * NH];       // ping-pong h state
__device__ unsigned g_bar[2];                    // spin-barrier counters (one per layer)

// ---------------- init: zero h state + barrier counters ----------------
__global__ void init_state() {
    int t = blockIdx.x * blockDim.x + threadIdx.x;
    int nthr = gridDim.x * blockDim.x;
    for (int i = t; i < 2 * BATCH * NH; i += nthr)
        ((float*)g_hbuf)[i] = 0.f;
    if (t < 2) g_bar[t] = 0u;
}

// ---------------- gx GEMM: gx[m][n] = bias[n] + sum_d A[m][d] * Wx[d][n] ----------------
// A row m: layer0 -> embed_W[tokens[m]], layer1 -> g_h1seq[m]. M=8192, K=256, N=1024.
__global__ __launch_bounds__(256) void gemm_gx(
    const float* __restrict__ embed_W,
    const int*   __restrict__ tokens,
    const float* __restrict__ Wx,      // [256][1024] row-major
    const float* __restrict__ bias,    // [1024]
    int layer)
{
    __shared__ float As[16][132];   // k-major (transposed) A tile
    __shared__ float Bs[16][132];   // k-major B tile

    const int m0 = blockIdx.y * 128;
    const int n0 = blockIdx.x * 128;
    const int t  = threadIdx.x;
    const int tx = t & 15;
    const int ty = t >> 4;

    // rows this thread loads for the A tile (fixed across k-tiles)
    const int r0 = t >> 2;          // 0..63
    const int r1 = r0 + 64;
    const int kq = (t & 3) * 4;
    const float* ap0;
    const float* ap1;
    if (layer == 0) {
        ap0 = embed_W + (size_t)tokens[m0 + r0] * NH;
        ap1 = embed_W + (size_t)tokens[m0 + r1] * NH;
    } else {
        ap0 = g_h1seq + (size_t)(m0 + r0) * NH;
        ap1 = g_h1seq + (size_t)(m0 + r1) * NH;
    }

    float acc[8][8];
    #pragma unroll
    for (int i = 0; i < 8; i++)
        #pragma unroll
        for (int j = 0; j < 8; j++) acc[i][j] = 0.f;

    for (int k0 = 0; k0 < NH; k0 += 16) {
        // A tile: 128 rows x 16 k, stored transposed
        {
            float4 v0 = *(const float4*)(ap0 + k0 + kq);
            float4 v1 = *(const float4*)(ap1 + k0 + kq);
            As[kq + 0][r0] = v0.x; As[kq + 1][r0] = v0.y;
            As[kq + 2][r0] = v0.z; As[kq + 3][r0] = v0.w;
            As[kq + 0][r1] = v1.x; As[kq + 1][r1] = v1.y;
            As[kq + 2][r1] = v1.z; As[kq + 3][r1] = v1.w;
        }
        // B tile: Wx[k0+kk][n0 + 0..127], naturally k-major
        #pragma unroll
        for (int i = 0; i < 2; i++) {
            int lin = t + i * 256;          // float4 units, 0..511
            int kk  = lin >> 5;             // 0..15
            int nq  = (lin & 31) * 4;
            *(float4*)&Bs[kk][nq] = *(const float4*)(Wx + (size_t)(k0 + kk) * NG + n0 + nq);
        }
        __syncthreads();
        #pragma unroll
        for (int kk = 0; kk < 16; kk++) {
            float a[8], b[8];
            *(float4*)&a[0] = *(const float4*)&As[kk][ty * 8];
            *(float4*)&a[4] = *(const float4*)&As[kk][ty * 8 + 4];
            *(float4*)&b[0] = *(const float4*)&Bs[kk][tx * 8];
            *(float4*)&b[4] = *(const float4*)&Bs[kk][tx * 8 + 4];
            #pragma unroll
            for (int i = 0; i < 8; i++)
                #pragma unroll
                for (int j = 0; j < 8; j++)
                    acc[i][j] += a[i] * b[j];
        }
        __syncthreads();
    }

    #pragma unroll
    for (int i = 0; i < 8; i++) {
        size_t m = (size_t)(m0 + ty * 8 + i);
        float* op = g_gx + m * NG + n0 + tx * 8;
        const float* bp = bias + n0 + tx * 8;
        #pragma unroll
        for (int j = 0; j < 8; j++) op[j] = acc[i][j] + bp[j];
    }
}

// ---------------- LSTM recurrence (persistent, grid spin-barrier) ----------------
// 128 CTAs x 256 threads. CTA owns 8 consecutive gate-columns (kg), all 32 batches.
// thread t: kgl = t&7, b = t>>3. Gate-group of a cell = 4 adjacent lanes -> shuffles.
__global__ __launch_bounds__(256) void lstm_layer(
    const float* __restrict__ Wh,   // [256][1024]
    float*       __restrict__ hout, // [32][256] final hidden -> d_out
    int layer)
{
    __shared__ float Whs[8][264];
    __shared__ float hs[32][264];

    const int t   = threadIdx.x;
    const int kg0 = blockIdx.x * 8;
    const int kgl = t & 7;
    const int b   = t >> 3;
    const int k   = (kg0 + kgl) >> 2;
    const bool owner = (t & 3) == 0;       // gate 0 lane of each cell

    float* hseq = layer ? g_h2seq : g_h1seq;
    unsigned* bar = &g_bar[layer];

    // Wh slice resident in SMEM for the whole sequence
    for (int idx = t; idx < 8 * NH; idx += 256) {
        int j = idx >> 3, c = idx & 7;
        Whs[c][j] = Wh[(size_t)j * NG + kg0 + c];
    }

    float cstate = 0.f;
    const unsigned lane = t & 31;
    const unsigned base = lane & ~3u;

    for (int s = 0; s < SEQ; s++) {
        __syncthreads();   // previous step's hs reads done before refill
        // fill full h state (32x256) from ping-pong buffer
        const float4* src = (const float4*)g_hbuf[s & 1];
        #pragma unroll
        for (int i = 0; i < 8; i++) {
            int idx = t + i * 256;          // 0..2047 float4 units
            float4 v = src[idx];
            int bb = idx >> 6;
            int jj = (idx & 63) * 4;
            *(float4*)&hs[bb][jj] = v;
        }
        __syncthreads();

        float z = g_gx[(size_t)s * BATCH * NG + (size_t)b * NG + kg0 + kgl];
        #pragma unroll 16
        for (int j = 0; j < NH; j += 4) {
            float4 hv = *(const float4*)&hs[b][j];
            float4 wv = *(const float4*)&Whs[kgl][j];
            z += hv.x * wv.x + hv.y * wv.y + hv.z * wv.z + hv.w * wv.w;
        }

        float zi = __shfl_sync(0xffffffffu, z, base + 0);
        float zf = __shfl_sync(0xffffffffu, z, base + 1);
        float zo = __shfl_sync(0xffffffffu, z, base + 2);
        float zg = __shfl_sync(0xffffffffu, z, base + 3);

        if (owner) {
            float ig = 1.f / (1.f + __expf(-zi));
            float fg = 1.f / (1.f + __expf(-zf));
            float og = 1.f / (1.f + __expf(-zo));
            float gg = tanhf(zg);
            cstate   = fg * cstate + ig * gg;
            float hn = og * tanhf(cstate);
            g_hbuf[(s + 1) & 1][b * NH + k] = hn;
            hseq[(size_t)s * BATCH * NH + b * NH + k] = hn;
            if (s == SEQ - 1) hout[b * NH + k] = hn;
            __threadfence();
        }
        __syncthreads();
        if (t == 0) {
            atomicAdd(bar, 1u);
            unsigned tgt = (unsigned)(s + 1) * gridDim.x;
            while (*(volatile unsigned*)bar < tgt) { }
            __threadfence();
        }
        __syncthreads();
    }
}

// ---------------- decoder GEMM (NT): out[m][v] = sum_h h2[m][h]*W[v][h] + bias[v] ----------------
__global__ __launch_bounds__(256) void gemm_dec(
    const float* __restrict__ W,     // [10000][256]
    const float* __restrict__ bias,  // [10000]
    float*       __restrict__ out)   // [8192][10000]
{
    __shared__ float As[16][132];
    __shared__ float Bs[16][132];

    const int m0 = blockIdx.y * 128;
    const int n0 = blockIdx.x * 128;
    const int t  = threadIdx.x;
    const int tx = t & 15;
    const int ty = t >> 4;

    const int r0 = t >> 2;
    const int r1 = r0 + 64;
    const int kq = (t & 3) * 4;
    const float* ap0 = g_h2seq + (size_t)(m0 + r0) * NH;
    const float* ap1 = g_h2seq + (size_t)(m0 + r1) * NH;
    const int n_r0 = n0 + r0;
    const int n_r1 = n0 + r1;

    float acc[8][8];
    #pragma unroll
    for (int i = 0; i < 8; i++)
        #pragma unroll
        for (int j = 0; j < 8; j++) acc[i][j] = 0.f;

    for (int k0 = 0; k0 < NH; k0 += 16) {
        {
            float4 v0 = *(const float4*)(ap0 + k0 + kq);
            float4 v1 = *(const float4*)(ap1 + k0 + kq);
            As[kq + 0][r0] = v0.x; As[kq + 1][r0] = v0.y;
            As[kq + 2][r0] = v0.z; As[kq + 3][r0] = v0.w;
            As[kq + 0][r1] = v1.x; As[kq + 1][r1] = v1.y;
            As[kq + 2][r1] = v1.z; As[kq + 3][r1] = v1.w;
        }
        {
            float4 z4 = make_float4(0.f, 0.f, 0.f, 0.f);
            float4 w0 = (n_r0 < NVOC) ? *(const float4*)(W + (size_t)n_r0 * NH + k0 + kq) : z4;
            float4 w1 = (n_r1 < NVOC) ? *(const float4*)(W + (size_t)n_r1 * NH + k0 + kq) : z4;
            Bs[kq + 0][r0] = w0.x; Bs[kq + 1][r0] = w0.y;
            Bs[kq + 2][r0] = w0.z; Bs[kq + 3][r0] = w0.w;
            Bs[kq + 0][r1] = w1.x; Bs[kq + 1][r1] = w1.y;
            Bs[kq + 2][r1] = w1.z; Bs[kq + 3][r1] = w1.w;
        }
        __syncthreads();
        #pragma unroll
        for (int kk = 0; kk < 16; kk++) {
            float a[8], b[8];
            *(float4*)&a[0] = *(const float4*)&As[kk][ty * 8];
            *(float4*)&a[4] = *(const float4*)&As[kk][ty * 8 + 4];
            *(float4*)&b[0] = *(const float4*)&Bs[kk][tx * 8];
            *(float4*)&b[4] = *(const float4*)&Bs[kk][tx * 8 + 4];
            #pragma unroll
            for (int i = 0; i < 8; i++)
                #pragma unroll
                for (int j = 0; j < 8; j++)
                    acc[i][j] += a[i] * b[j];
        }
        __syncthreads();
    }

    #pragma unroll
    for (int i = 0; i < 8; i++) {
        size_t m = (size_t)(m0 + ty * 8 + i);
        int nb = n0 + tx * 8;
        float* op = out + m * NVOC + nb;
        if (nb + 8 <= NVOC) {
            float4 o0, o1;
            o0.x = acc[i][0] + bias[nb + 0]; o0.y = acc[i][1] + bias[nb + 1];
            o0.z = acc[i][2] + bias[nb + 2]; o0.w = acc[i][3] + bias[nb + 3];
            o1.x = acc[i][4] + bias[nb + 4]; o1.y = acc[i][5] + bias[nb + 5];
            o1.z = acc[i][6] + bias[nb + 6]; o1.w = acc[i][7] + bias[nb + 7];
            // NVOC=10000 rows not 16B aligned per-row (10000*4 % 16 == 0 actually),
            // but nb alignment (multiple of 8 floats) + row offset m*10000 keeps 16B: 10000%4==0 -> ok
            *(float4*)(op + 0) = o0;
            *(float4*)(op + 4) = o1;
        } else {
            #pragma unroll
            for (int j = 0; j < 8; j++) {
                int n = nb + j;
                if (n < NVOC) op[j] = acc[i][j] + bias[n];
            }
        }
    }
}

// ---------------- launch ----------------
extern "C" void kernel_launch(void* const* d_in, const int* in_sizes, int n_in,
                              void* d_out, int out_size) {
    const int*   tokens  = (const int*)  d_in[0];
    const float* embed_W = (const float*)d_in[1];
    const float* Wx0     = (const float*)d_in[2];
    const float* Wh0     = (const float*)d_in[3];
    const float* b0      = (const float*)d_in[4];
    const float* Wx1     = (const float*)d_in[5];
    const float* Wh1     = (const float*)d_in[6];
    const float* b1      = (const float*)d_in[7];
    const float* dec_W   = (const float*)d_in[8];
    const float* dec_b   = (const float*)d_in[9];
    (void)in_sizes; (void)n_in;

    float* out    = (float*)d_out;
    float* h1_out = out + (size_t)out_size - 2 * BATCH * NH;
    float* h2_out = out + (size_t)out_size - 1 * BATCH * NH;

    // layer 0
    init_state<<<16, 256>>>();
    gemm_gx<<<dim3(8, 64), 256>>>(embed_W, tokens, Wx0, b0, 0);
    lstm_layer<<<128, 256>>>(Wh0, h1_out, 0);

    // layer 1
    init_state<<<16, 256>>>();
    gemm_gx<<<dim3(8, 64), 256>>>(embed_W, tokens, Wx1, b1, 1);
    lstm_layer<<<128, 256>>>(Wh1, h2_out, 1);

    // decoder
    gemm_dec<<<dim3(79, 64), 256>>>(dec_W, dec_b, out);
}

// round 2
// speedup vs baseline: 1.1605x; 1.1605x over previous
#include <cuda_runtime.h>
#include <cuda_bf16.h>
#include <cstdint>
#include <cstddef>

#define SEQ   256
#define BATCH 32
#define NVOC  10000
#define NVPAD 10112     // 79 * 128
#define NH    256
#define NG    1024      // NH * 4 gates
#define MTOT  8192      // SEQ * BATCH

// ---------------- scratch (static device globals; no allocation) ----------------
__device__ float    g_gx[(size_t)MTOT * NG];     // gate inputs, reused by both layers (32 MB)
__device__ float    g_h1seq[(size_t)MTOT * NH];  // layer-0 hidden sequence
__device__ float    g_h2seq[(size_t)MTOT * NH];  // layer-1 hidden sequence
__device__ float    g_hbuf[2][BATCH * NH];       // ping-pong h state
__device__ unsigned g_bar[2];                    // spin-barrier counters (one per layer)

// bf16 split buffers for tensor-core decoder
__device__ __nv_bfloat16 g_Ahi[(size_t)MTOT * NH];
__device__ __nv_bfloat16 g_Alo[(size_t)MTOT * NH];
__device__ __nv_bfloat16 g_Whi[(size_t)NVPAD * NH];
__device__ __nv_bfloat16 g_Wlo[(size_t)NVPAD * NH];

// ---------------- init: zero h state + barrier counters ----------------
__global__ void init_state() {
    int t = blockIdx.x * blockDim.x + threadIdx.x;
    int nthr = gridDim.x * blockDim.x;
    for (int i = t; i < 2 * BATCH * NH; i += nthr)
        ((float*)g_hbuf)[i] = 0.f;
    if (t < 2) g_bar[t] = 0u;
}

// ---------------- gx GEMM: gx[m][n] = bias[n] + sum_d A[m][d] * Wx[d][n] ----------------
__global__ __launch_bounds__(256) void gemm_gx(
    const float* __restrict__ embed_W,
    const int*   __restrict__ tokens,
    const float* __restrict__ Wx,      // [256][1024] row-major
    const float* __restrict__ bias,    // [1024]
    int layer)
{
    __shared__ float As[16][132];
    __shared__ float Bs[16][132];

    const int m0 = blockIdx.y * 128;
    const int n0 = blockIdx.x * 128;
    const int t  = threadIdx.x;
    const int tx = t & 15;
    const int ty = t >> 4;

    const int r0 = t >> 2;
    const int r1 = r0 + 64;
    const int kq = (t & 3) * 4;
    const float* ap0;
    const float* ap1;
    if (layer == 0) {
        ap0 = embed_W + (size_t)tokens[m0 + r0] * NH;
        ap1 = embed_W + (size_t)tokens[m0 + r1] * NH;
    } else {
        ap0 = g_h1seq + (size_t)(m0 + r0) * NH;
        ap1 = g_h1seq + (size_t)(m0 + r1) * NH;
    }

    float acc[8][8];
    #pragma unroll
    for (int i = 0; i < 8; i++)
        #pragma unroll
        for (int j = 0; j < 8; j++) acc[i][j] = 0.f;

    for (int k0 = 0; k0 < NH; k0 += 16) {
        {
            float4 v0 = *(const float4*)(ap0 + k0 + kq);
            float4 v1 = *(const float4*)(ap1 + k0 + kq);
            As[kq + 0][r0] = v0.x; As[kq + 1][r0] = v0.y;
            As[kq + 2][r0] = v0.z; As[kq + 3][r0] = v0.w;
            As[kq + 0][r1] = v1.x; As[kq + 1][r1] = v1.y;
            As[kq + 2][r1] = v1.z; As[kq + 3][r1] = v1.w;
        }
        #pragma unroll
        for (int i = 0; i < 2; i++) {
            int lin = t + i * 256;
            int kk  = lin >> 5;
            int nq  = (lin & 31) * 4;
            *(float4*)&Bs[kk][nq] = *(const float4*)(Wx + (size_t)(k0 + kk) * NG + n0 + nq);
        }
        __syncthreads();
        #pragma unroll
        for (int kk = 0; kk < 16; kk++) {
            float a[8], b[8];
            *(float4*)&a[0] = *(const float4*)&As[kk][ty * 8];
            *(float4*)&a[4] = *(const float4*)&As[kk][ty * 8 + 4];
            *(float4*)&b[0] = *(const float4*)&Bs[kk][tx * 8];
            *(float4*)&b[4] = *(const float4*)&Bs[kk][tx * 8 + 4];
            #pragma unroll
            for (int i = 0; i < 8; i++)
                #pragma unroll
                for (int j = 0; j < 8; j++)
                    acc[i][j] += a[i] * b[j];
        }
        __syncthreads();
    }

    #pragma unroll
    for (int i = 0; i < 8; i++) {
        size_t m = (size_t)(m0 + ty * 8 + i);
        float* op = g_gx + m * NG + n0 + tx * 8;
        const float* bp = bias + n0 + tx * 8;
        #pragma unroll
        for (int j = 0; j < 8; j++) op[j] = acc[i][j] + bp[j];
    }
}

// ---------------- LSTM recurrence (persistent, grid spin-barrier) ----------------
__global__ __launch_bounds__(256) void lstm_layer(
    const float* __restrict__ Wh,   // [256][1024]
    float*       __restrict__ hout, // [32][256]
    int layer)
{
    __shared__ float Whs[8][264];
    __shared__ float hs[32][264];

    const int t   = threadIdx.x;
    const int kg0 = blockIdx.x * 8;
    const int kgl = t & 7;
    const int b   = t >> 3;
    const int k   = (kg0 + kgl) >> 2;
    const bool owner = (t & 3) == 0;

    float* hseq = layer ? g_h2seq : g_h1seq;
    unsigned* bar = &g_bar[layer];

    for (int idx = t; idx < 8 * NH; idx += 256) {
        int j = idx >> 3, c = idx & 7;
        Whs[c][j] = Wh[(size_t)j * NG + kg0 + c];
    }

    float cstate = 0.f;
    const unsigned lane = t & 31;
    const unsigned base = lane & ~3u;

    for (int s = 0; s < SEQ; s++) {
        __syncthreads();
        const float4* src = (const float4*)g_hbuf[s & 1];
        #pragma unroll
        for (int i = 0; i < 8; i++) {
            int idx = t + i * 256;
            float4 v = src[idx];
            int bb = idx >> 6;
            int jj = (idx & 63) * 4;
            *(float4*)&hs[bb][jj] = v;
        }
        __syncthreads();

        float z = g_gx[(size_t)s * BATCH * NG + (size_t)b * NG + kg0 + kgl];
        #pragma unroll 16
        for (int j = 0; j < NH; j += 4) {
            float4 hv = *(const float4*)&hs[b][j];
            float4 wv = *(const float4*)&Whs[kgl][j];
            z += hv.x * wv.x + hv.y * wv.y + hv.z * wv.z + hv.w * wv.w;
        }

        float zi = __shfl_sync(0xffffffffu, z, base + 0);
        float zf = __shfl_sync(0xffffffffu, z, base + 1);
        float zo = __shfl_sync(0xffffffffu, z, base + 2);
        float zg = __shfl_sync(0xffffffffu, z, base + 3);

        if (owner) {
            float ig = 1.f / (1.f + __expf(-zi));
            float fg = 1.f / (1.f + __expf(-zf));
            float og = 1.f / (1.f + __expf(-zo));
            float gg = tanhf(zg);
            cstate   = fg * cstate + ig * gg;
            float hn = og * tanhf(cstate);
            g_hbuf[(s + 1) & 1][b * NH + k] = hn;
            hseq[(size_t)s * BATCH * NH + b * NH + k] = hn;
            if (s == SEQ - 1) hout[b * NH + k] = hn;
            __threadfence();
        }
        __syncthreads();
        if (t == 0) {
            atomicAdd(bar, 1u);
            unsigned tgt = (unsigned)(s + 1) * gridDim.x;
            while (*(volatile unsigned*)bar < tgt) { }
            __threadfence();
        }
        __syncthreads();
    }
}

// ---------------- bf16 split conversions ----------------
__global__ __launch_bounds__(256) void conv_A() {
    int i = blockIdx.x * blockDim.x + threadIdx.x;
    if (i < MTOT * NH) {
        float x = g_h2seq[i];
        __nv_bfloat16 hi = __float2bfloat16_rn(x);
        g_Ahi[i] = hi;
        g_Alo[i] = __float2bfloat16_rn(x - __bfloat162float(hi));
    }
}

__global__ __launch_bounds__(256) void conv_W(const float* __restrict__ W) {
    int i = blockIdx.x * blockDim.x + threadIdx.x;
    if (i < NVPAD * NH) {
        int v = i >> 8;
        float x = (v < NVOC) ? W[(size_t)v * NH + (i & 255)] : 0.f;
        __nv_bfloat16 hi = __float2bfloat16_rn(x);
        g_Whi[i] = hi;
        g_Wlo[i] = __float2bfloat16_rn(x - __bfloat162float(hi));
    }
}

// ---------------- tensor-core decoder GEMM (split-bf16, 3 products) ----------------
// out[m][v] = sum_h A[m][h] * W[v][h] + bias[v];   A=h2seq (fp32 split), W=dec_W (split)
// CTA: 128(M) x 128(N), 8 warps as 2(M)x4(N), warp tile 64x32. K-chunk 32.
#define LDM_A(r0,r1,r2,r3,addr) \
    asm volatile("ldmatrix.sync.aligned.m8n8.x4.shared.b16 {%0,%1,%2,%3}, [%4];" \
        : "=r"(r0), "=r"(r1), "=r"(r2), "=r"(r3) : "r"(addr))

#define MMA_BF16(c, a, b) \
    asm volatile("mma.sync.aligned.m16n8k16.row.col.f32.bf16.bf16.f32 " \
        "{%0,%1,%2,%3}, {%4,%5,%6,%7}, {%8,%9}, {%0,%1,%2,%3};" \
        : "+f"((c)[0]), "+f"((c)[1]), "+f"((c)[2]), "+f"((c)[3]) \
        : "r"((a)[0]), "r"((a)[1]), "r"((a)[2]), "r"((a)[3]), "r"((b)[0]), "r"((b)[1]))

__global__ __launch_bounds__(256) void gemm_dec_tc(
    const float* __restrict__ bias,
    float*       __restrict__ out)
{
    __shared__ __nv_bfloat16 sAhi[128][40];
    __shared__ __nv_bfloat16 sAlo[128][40];
    __shared__ __nv_bfloat16 sBhi[128][40];
    __shared__ __nv_bfloat16 sBlo[128][40];

    const int t    = threadIdx.x;
    const int warp = t >> 5;
    const int lane = t & 31;
    const int m0   = blockIdx.y * 128;
    const int n0   = blockIdx.x * 128;
    const int wm   = warp >> 2;          // 0..1 : 64-row slab
    const int wn   = warp & 3;           // 0..3 : 32-col slab

    // global load mapping: 512 16B-chunks per tile, 2 per thread
    const int lrow0 = t >> 1;                 // chunks t*? -> row = cc>>2
    (void)lrow0;

    float acc[4][4][4];
    #pragma unroll
    for (int i = 0; i < 4; i++)
        #pragma unroll
        for (int j = 0; j < 4; j++)
            #pragma unroll
            for (int q = 0; q < 4; q++) acc[i][j][q] = 0.f;

    // precomputed shared base addresses (32-bit shared-space)
    const uint32_t bAhi = (uint32_t)__cvta_generic_to_shared(&sAhi[0][0]);
    const uint32_t bAlo = (uint32_t)__cvta_generic_to_shared(&sAlo[0][0]);
    const uint32_t bBhi = (uint32_t)__cvta_generic_to_shared(&sBhi[0][0]);
    const uint32_t bBlo = (uint32_t)__cvta_generic_to_shared(&sBlo[0][0]);

    // ldmatrix per-lane row/k offsets
    const int a_row = (lane & 15);                        // 0..15
    const int a_k   = (lane >> 4) * 8;                    // 0 or 8
    const int b_row = (lane & 7) + ((lane >> 4) << 3);    // 0..15
    const int b_k   = ((lane >> 3) & 1) * 8;              // 0 or 8

    for (int kc = 0; kc < 8; kc++) {
        const int k0 = kc * 32;
        // ---- load tiles (each thread: 2 chunks x 4 tiles) ----
        #pragma unroll
        for (int h = 0; h < 2; h++) {
            int cc  = t + h * 256;       // 0..511
            int row = cc >> 2;           // 0..127
            int q   = cc & 3;            // 16B chunk within 32 k-elems
            size_t gA = (size_t)(m0 + row) * NH + k0 + q * 8;
            size_t gB = (size_t)(n0 + row) * NH + k0 + q * 8;
            *(uint4*)&sAhi[row][q * 8] = *(const uint4*)(g_Ahi + gA);
            *(uint4*)&sAlo[row][q * 8] = *(const uint4*)(g_Alo + gA);
            *(uint4*)&sBhi[row][q * 8] = *(const uint4*)(g_Whi + gB);
            *(uint4*)&sBlo[row][q * 8] = *(const uint4*)(g_Wlo + gB);
        }
        __syncthreads();

        #pragma unroll
        for (int ks = 0; ks < 32; ks += 16) {
            uint32_t af[4][4];   // 4 m16 frags
            uint32_t bh[4][2], bl[4][2];

            // B frags (hi & lo): 2 ldmatrix.x4 each cover two n8 tiles
            #pragma unroll
            for (int nh = 0; nh < 2; nh++) {
                int roff = (wn * 32 + nh * 16 + b_row) * 40 + ks + b_k;
                uint32_t r0, r1, r2, r3;
                LDM_A(r0, r1, r2, r3, bBhi + roff * 2);
                bh[2*nh][0] = r0; bh[2*nh][1] = r1;
                bh[2*nh+1][0] = r2; bh[2*nh+1][1] = r3;
                LDM_A(r0, r1, r2, r3, bBlo + roff * 2);
                bl[2*nh][0] = r0; bl[2*nh][1] = r1;
                bl[2*nh+1][0] = r2; bl[2*nh+1][1] = r3;
            }

            // A hi frags
            #pragma unroll
            for (int mi = 0; mi < 4; mi++) {
                int roff = (wm * 64 + mi * 16 + a_row) * 40 + ks + a_k;
                LDM_A(af[mi][0], af[mi][1], af[mi][2], af[mi][3], bAhi + roff * 2);
            }
            // Ahi*Bhi + Ahi*Blo
            #pragma unroll
            for (int mi = 0; mi < 4; mi++)
                #pragma unroll
                for (int ni = 0; ni < 4; ni++) {
                    MMA_BF16(acc[mi][ni], af[mi], bh[ni]);
                    MMA_BF16(acc[mi][ni], af[mi], bl[ni]);
                }
            // A lo frags
            #pragma unroll
            for (int mi = 0; mi < 4; mi++) {
                int roff = (wm * 64 + mi * 16 + a_row) * 40 + ks + a_k;
                LDM_A(af[mi][0], af[mi][1], af[mi][2], af[mi][3], bAlo + roff * 2);
            }
            // Alo*Bhi
            #pragma unroll
            for (int mi = 0; mi < 4; mi++)
                #pragma unroll
                for (int ni = 0; ni < 4; ni++)
                    MMA_BF16(acc[mi][ni], af[mi], bh[ni]);
        }
        __syncthreads();
    }

    // ---- epilogue ----
    const int g  = lane >> 2;
    const int t4 = lane & 3;
    #pragma unroll
    for (int mi = 0; mi < 4; mi++) {
        #pragma unroll
        for (int ni = 0; ni < 4; ni++) {
            int col = n0 + wn * 32 + ni * 8 + t4 * 2;
            if (col < NVOC) {
                float b0 = bias[col], b1 = bias[col + 1];
                int row0 = m0 + wm * 64 + mi * 16 + g;
                float2 v0 = make_float2(acc[mi][ni][0] + b0, acc[mi][ni][1] + b1);
                float2 v1 = make_float2(acc[mi][ni][2] + b0, acc[mi][ni][3] + b1);
                *(float2*)(out + (size_t)row0 * NVOC + col) = v0;
                *(float2*)(out + (size_t)(row0 + 8) * NVOC + col) = v1;
            }
        }
    }
}

// ---------------- launch ----------------
extern "C" void kernel_launch(void* const* d_in, const int* in_sizes, int n_in,
                              void* d_out, int out_size) {
    const int*   tokens  = (const int*)  d_in[0];
    const float* embed_W = (const float*)d_in[1];
    const float* Wx0     = (const float*)d_in[2];
    const float* Wh0     = (const float*)d_in[3];
    const float* b0      = (const float*)d_in[4];
    const float* Wx1     = (const float*)d_in[5];
    const float* Wh1     = (const float*)d_in[6];
    const float* b1      = (const float*)d_in[7];
    const float* dec_W   = (const float*)d_in[8];
    const float* dec_b   = (const float*)d_in[9];
    (void)in_sizes; (void)n_in;

    float* out    = (float*)d_out;
    float* h1_out = out + (size_t)out_size - 2 * BATCH * NH;
    float* h2_out = out + (size_t)out_size - 1 * BATCH * NH;

    // W split can run first (independent)
    conv_W<<<(NVPAD * NH + 255) / 256, 256>>>(dec_W);

    // layer 0
    init_state<<<16, 256>>>();
    gemm_gx<<<dim3(8, 64), 256>>>(embed_W, tokens, Wx0, b0, 0);
    lstm_layer<<<128, 256>>>(Wh0, h1_out, 0);

    // layer 1
    init_state<<<16, 256>>>();
    gemm_gx<<<dim3(8, 64), 256>>>(embed_W, tokens, Wx1, b1, 1);
    lstm_layer<<<128, 256>>>(Wh1, h2_out, 1);

    // decoder: split h2 to bf16 pair, then tensor-core GEMM
    conv_A<<<(MTOT * NH + 255) / 256, 256>>>();
    gemm_dec_tc<<<dim3(79, 64), 256>>>(dec_b, out);
}

// round 4
// speedup vs baseline: 1.6322x; 1.4064x over previous
#include <cuda_runtime.h>
#include <cuda_bf16.h>
#include <cstdint>
#include <cstddef>

#define SEQ   256
#define BATCH 32
#define NVOC  10000
#define NVPAD 10112     // 79 * 128
#define NH    256
#define NG    1024      // NH * 4 gates
#define MTOT  8192      // SEQ * BATCH

// ---------------- scratch (static device globals; no allocation) ----------------
__device__ float    g_gx[(size_t)MTOT * NG];     // layer-0 gate inputs (32 MB)
__device__ float    g_h1buf[2][BATCH * NH];      // layer-0 h ping-pong
__device__ float    g_h2buf[2][BATCH * NH];      // layer-1 h ping-pong
__device__ unsigned g_cnt;                       // barrier arrival counter
__device__ unsigned g_flag;                      // barrier release flag

// bf16 split buffers for tensor-core decoder
__device__ __nv_bfloat16 g_Ahi[(size_t)MTOT * NH];
__device__ __nv_bfloat16 g_Alo[(size_t)MTOT * NH];
__device__ __nv_bfloat16 g_Whi[(size_t)NVPAD * NH];
__device__ __nv_bfloat16 g_Wlo[(size_t)NVPAD * NH];

// ---------------- init: zero h state + barrier ----------------
__global__ void init_state() {
    int t = blockIdx.x * blockDim.x + threadIdx.x;
    int nthr = gridDim.x * blockDim.x;
    for (int i = t; i < 2 * BATCH * NH; i += nthr) {
        ((float*)g_h1buf)[i] = 0.f;
        ((float*)g_h2buf)[i] = 0.f;
    }
    if (t == 0) { g_cnt = 0u; g_flag = 0u; }
}

// ---------------- gx GEMM (layer 0 only): gx[m][n] = b0[n] + x[m]·Wx0[:,n] ----------------
__global__ __launch_bounds__(256) void gemm_gx(
    const float* __restrict__ embed_W,
    const int*   __restrict__ tokens,
    const float* __restrict__ Wx,      // [256][1024]
    const float* __restrict__ bias)    // [1024]
{
    __shared__ float As[16][132];
    __shared__ float Bs[16][132];

    const int m0 = blockIdx.y * 128;
    const int n0 = blockIdx.x * 128;
    const int t  = threadIdx.x;
    const int tx = t & 15;
    const int ty = t >> 4;

    const int r0 = t >> 2;
    const int r1 = r0 + 64;
    const int kq = (t & 3) * 4;
    const float* ap0 = embed_W + (size_t)tokens[m0 + r0] * NH;
    const float* ap1 = embed_W + (size_t)tokens[m0 + r1] * NH;

    float acc[8][8];
    #pragma unroll
    for (int i = 0; i < 8; i++)
        #pragma unroll
        for (int j = 0; j < 8; j++) acc[i][j] = 0.f;

    for (int k0 = 0; k0 < NH; k0 += 16) {
        {
            float4 v0 = *(const float4*)(ap0 + k0 + kq);
            float4 v1 = *(const float4*)(ap1 + k0 + kq);
            As[kq + 0][r0] = v0.x; As[kq + 1][r0] = v0.y;
            As[kq + 2][r0] = v0.z; As[kq + 3][r0] = v0.w;
            As[kq + 0][r1] = v1.x; As[kq + 1][r1] = v1.y;
            As[kq + 2][r1] = v1.z; As[kq + 3][r1] = v1.w;
        }
        #pragma unroll
        for (int i = 0; i < 2; i++) {
            int lin = t + i * 256;
            int kk  = lin >> 5;
            int nq  = (lin & 31) * 4;
            *(float4*)&Bs[kk][nq] = *(const float4*)(Wx + (size_t)(k0 + kk) * NG + n0 + nq);
        }
        __syncthreads();
        #pragma unroll
        for (int kk = 0; kk < 16; kk++) {
            float a[8], b[8];
            *(float4*)&a[0] = *(const float4*)&As[kk][ty * 8];
            *(float4*)&a[4] = *(const float4*)&As[kk][ty * 8 + 4];
            *(float4*)&b[0] = *(const float4*)&Bs[kk][tx * 8];
            *(float4*)&b[4] = *(const float4*)&Bs[kk][tx * 8 + 4];
            #pragma unroll
            for (int i = 0; i < 8; i++)
                #pragma unroll
                for (int j = 0; j < 8; j++)
                    acc[i][j] += a[i] * b[j];
        }
        __syncthreads();
    }

    #pragma unroll
    for (int i = 0; i < 8; i++) {
        size_t m = (size_t)(m0 + ty * 8 + i);
        float* op = g_gx + m * NG + n0 + tx * 8;
        const float* bp = bias + n0 + tx * 8;
        #pragma unroll
        for (int j = 0; j < 8; j++) op[j] = acc[i][j] + bp[j];
    }
}

// ---------------- fused 2-layer LSTM recurrence (pipelined, persistent) ----------------
// 128 CTAs x 256 threads, 257 rounds. Round r: layer0 step r, layer1 step r-1.
// State tiles read parity (r&1), written parity ((r+1)&1) -> no intra-round aliasing.
#define WSTR   260
#define OFF_W0 0
#define OFF_WX (8  * WSTR)
#define OFF_W1 (16 * WSTR)
#define OFF_H1 (24 * WSTR)
#define OFF_H2 (56 * WSTR)
#define SMEM_FLOATS (88 * WSTR)
#define SMEM_BYTES  (SMEM_FLOATS * 4)

__global__ __launch_bounds__(256, 1) void fused_rnn(
    const float* __restrict__ Wh0,   // [256][1024]
    const float* __restrict__ Wx1,   // [256][1024]
    const float* __restrict__ Wh1,   // [256][1024]
    const float* __restrict__ b1,    // [1024]
    float*       __restrict__ h1_out,
    float*       __restrict__ h2_out)
{
    extern __shared__ float sm[];

    const int t   = threadIdx.x;
    const int kg0 = blockIdx.x * 8;
    const int c   = t & 7;
    const int b   = t >> 3;
    const int k   = (kg0 + c) >> 2;        // cell index for owner lanes
    const bool owner = (t & 3) == 0;
    const unsigned lane = t & 31;
    const unsigned base = lane & ~3u;
    const unsigned grid = gridDim.x;

    // load weight slices (resident for whole kernel)
    for (int idx = t; idx < 8 * NH; idx += 256) {
        int j = idx >> 3, cc = idx & 7;
        sm[OFF_W0 + cc * WSTR + j] = Wh0[(size_t)j * NG + kg0 + cc];
        sm[OFF_WX + cc * WSTR + j] = Wx1[(size_t)j * NG + kg0 + cc];
        sm[OFF_W1 + cc * WSTR + j] = Wh1[(size_t)j * NG + kg0 + cc];
    }
    const float b1v = b1[kg0 + c];

    const uint32_t sb  = (uint32_t)__cvta_generic_to_shared(sm);
    const uint32_t ah1 = sb + (OFF_H1 + b * WSTR) * 4;
    const uint32_t ah2 = sb + (OFF_H2 + b * WSTR) * 4;
    const uint32_t aw0 = sb + (OFF_W0 + c * WSTR) * 4;
    const uint32_t awx = sb + (OFF_WX + c * WSTR) * 4;
    const uint32_t aw1 = sb + (OFF_W1 + c * WSTR) * 4;

    float c1 = 0.f, c2 = 0.f;

    for (int r = 0; r <= SEQ; r++) {
        // prefetch gx (independent of barrier)
        int s0 = (r < SEQ) ? r : SEQ - 1;
        float gx0v = g_gx[(size_t)s0 * BATCH * NG + (size_t)b * NG + kg0 + c];

        // wait for previous round's h publication
        if (r > 0 && t == 0) {
            while (*(volatile unsigned*)&g_flag < (unsigned)r) { }
            __threadfence();
        }
        __syncthreads();

        // refill h1/h2 state tiles (L2-coherent loads; both read parity r&1)
        {
            const float4* s1p = (const float4*)g_h1buf[r & 1];
            const float4* s2p = (const float4*)g_h2buf[r & 1];
            #pragma unroll
            for (int i = 0; i < 8; i++) {
                int idx = t + i * 256;
                int bb = idx >> 6, jj = (idx & 63) * 4;
                *(float4*)&sm[OFF_H1 + bb * WSTR + jj] = __ldcg(s1p + idx);
                *(float4*)&sm[OFF_H2 + bb * WSTR + jj] = __ldcg(s2p + idx);
            }
        }
        __syncthreads();

        // three fused dot products (f32x2 packed FMA)
        unsigned long long z0a = 0, z0b = 0, zxa = 0, zxb = 0, z2a = 0, z2b = 0;
        #pragma unroll 8
        for (int j = 0; j < 64; j++) {
            int o = j * 16;
            unsigned long long h1a, h1b, h2a, h2b, w0a, w0b, wxa, wxb, w1a, w1b;
            asm volatile("ld.shared.v2.b64 {%0,%1},[%2];" : "=l"(h1a), "=l"(h1b) : "r"(ah1 + o));
            asm volatile("ld.shared.v2.b64 {%0,%1},[%2];" : "=l"(h2a), "=l"(h2b) : "r"(ah2 + o));
            asm volatile("ld.shared.v2.b64 {%0,%1},[%2];" : "=l"(w0a), "=l"(w0b) : "r"(aw0 + o));
            asm volatile("ld.shared.v2.b64 {%0,%1},[%2];" : "=l"(wxa), "=l"(wxb) : "r"(awx + o));
            asm volatile("ld.shared.v2.b64 {%0,%1},[%2];" : "=l"(w1a), "=l"(w1b) : "r"(aw1 + o));
            asm("fma.rn.f32x2 %0,%1,%2,%0;" : "+l"(z0a) : "l"(h1a), "l"(w0a));
            asm("fma.rn.f32x2 %0,%1,%2,%0;" : "+l"(z0b) : "l"(h1b), "l"(w0b));
            asm("fma.rn.f32x2 %0,%1,%2,%0;" : "+l"(zxa) : "l"(h1a), "l"(wxa));
            asm("fma.rn.f32x2 %0,%1,%2,%0;" : "+l"(zxb) : "l"(h1b), "l"(wxb));
            asm("fma.rn.f32x2 %0,%1,%2,%0;" : "+l"(z2a) : "l"(h2a), "l"(w1a));
            asm("fma.rn.f32x2 %0,%1,%2,%0;" : "+l"(z2b) : "l"(h2b), "l"(w1b));
        }

        float z0, z1;
        {
            float lo, hi, s;
            asm("mov.b64 {%0,%1},%2;" : "=f"(lo), "=f"(hi) : "l"(z0a)); s  = lo + hi;
            asm("mov.b64 {%0,%1},%2;" : "=f"(lo), "=f"(hi) : "l"(z0b)); s += lo + hi;
            z0 = gx0v + s;
            asm("mov.b64 {%0,%1},%2;" : "=f"(lo), "=f"(hi) : "l"(zxa)); s  = lo + hi;
            asm("mov.b64 {%0,%1},%2;" : "=f"(lo), "=f"(hi) : "l"(zxb)); s += lo + hi;
            asm("mov.b64 {%0,%1},%2;" : "=f"(lo), "=f"(hi) : "l"(z2a)); s += lo + hi;
            asm("mov.b64 {%0,%1},%2;" : "=f"(lo), "=f"(hi) : "l"(z2b)); s += lo + hi;
            z1 = b1v + s;
        }

        // gather 4 gates per cell via shuffles (uniform flow)
        float zi0 = __shfl_sync(0xffffffffu, z0, base + 0);
        float zf0 = __shfl_sync(0xffffffffu, z0, base + 1);
        float zo0 = __shfl_sync(0xffffffffu, z0, base + 2);
        float zg0 = __shfl_sync(0xffffffffu, z0, base + 3);
        float zi1 = __shfl_sync(0xffffffffu, z1, base + 0);
        float zf1 = __shfl_sync(0xffffffffu, z1, base + 1);
        float zo1 = __shfl_sync(0xffffffffu, z1, base + 2);
        float zg1 = __shfl_sync(0xffffffffu, z1, base + 3);

        if (owner) {
            if (r < SEQ) {      // layer 0 step r
                float ig = 1.f / (1.f + __expf(-zi0));
                float fg = 1.f / (1.f + __expf(-zf0));
                float og = 1.f / (1.f + __expf(-zo0));
                float gg = tanhf(zg0);
                c1 = fg * c1 + ig * gg;
                float hn = og * tanhf(c1);
                g_h1buf[(r + 1) & 1][b * NH + k] = hn;
                if (r == SEQ - 1) h1_out[b * NH + k] = hn;
            }
            if (r >= 1) {       // layer 1 step r-1
                int s1 = r - 1;
                float ig = 1.f / (1.f + __expf(-zi1));
                float fg = 1.f / (1.f + __expf(-zf1));
                float og = 1.f / (1.f + __expf(-zo1));
                float gg = tanhf(zg1);
                c2 = fg * c2 + ig * gg;
                float hn = og * tanhf(c2);
                g_h2buf[(r + 1) & 1][b * NH + k] = hn;
                size_t m = (size_t)s1 * BATCH + b;
                __nv_bfloat16 hb = __float2bfloat16_rn(hn);
                g_Ahi[m * NH + k] = hb;
                g_Alo[m * NH + k] = __float2bfloat16_rn(hn - __bfloat162float(hb));
                if (s1 == SEQ - 1) h2_out[b * NH + k] = hn;
            }
        }

        // arrive (not needed after final round)
        if (r < SEQ) {
            __syncthreads();
            if (t == 0) {
                __threadfence();
                unsigned old = atomicAdd(&g_cnt, 1u);
                if (old == (unsigned)r * grid + grid - 1u)
                    atomicExch(&g_flag, (unsigned)(r + 1));
            }
        }
    }
}

// ---------------- bf16 split of decoder weights ----------------
__global__ __launch_bounds__(256) void conv_W(const float* __restrict__ W) {
    int i = blockIdx.x * blockDim.x + threadIdx.x;
    if (i < NVPAD * NH) {
        int v = i >> 8;
        float x = (v < NVOC) ? W[(size_t)v * NH + (i & 255)] : 0.f;
        __nv_bfloat16 hi = __float2bfloat16_rn(x);
        g_Whi[i] = hi;
        g_Wlo[i] = __float2bfloat16_rn(x - __bfloat162float(hi));
    }
}

// ---------------- tensor-core decoder GEMM (split-bf16, 3 products) ----------------
#define LDM_A(r0,r1,r2,r3,addr) \
    asm volatile("ldmatrix.sync.aligned.m8n8.x4.shared.b16 {%0,%1,%2,%3}, [%4];" \
        : "=r"(r0), "=r"(r1), "=r"(r2), "=r"(r3) : "r"(addr))

#define MMA_BF16(c, a, b) \
    asm volatile("mma.sync.aligned.m16n8k16.row.col.f32.bf16.bf16.f32 " \
        "{%0,%1,%2,%3}, {%4,%5,%6,%7}, {%8,%9}, {%0,%1,%2,%3};" \
        : "+f"((c)[0]), "+f"((c)[1]), "+f"((c)[2]), "+f"((c)[3]) \
        : "r"((a)[0]), "r"((a)[1]), "r"((a)[2]), "r"((a)[3]), "r"((b)[0]), "r"((b)[1]))

__global__ __launch_bounds__(256) void gemm_dec_tc(
    const float* __restrict__ bias,
    float*       __restrict__ out)
{
    __shared__ __nv_bfloat16 sAhi[128][40];
    __shared__ __nv_bfloat16 sAlo[128][40];
    __shared__ __nv_bfloat16 sBhi[128][40];
    __shared__ __nv_bfloat16 sBlo[128][40];

    const int t    = threadIdx.x;
    const int warp = t >> 5;
    const int lane = t & 31;
    const int m0   = blockIdx.y * 128;
    const int n0   = blockIdx.x * 128;
    const int wm   = warp >> 2;
    const int wn   = warp & 3;

    float acc[4][4][4];
    #pragma unroll
    for (int i = 0; i < 4; i++)
        #pragma unroll
        for (int j = 0; j < 4; j++)
            #pragma unroll
            for (int q = 0; q < 4; q++) acc[i][j][q] = 0.f;

    const uint32_t bAhi = (uint32_t)__cvta_generic_to_shared(&sAhi[0][0]);
    const uint32_t bAlo = (uint32_t)__cvta_generic_to_shared(&sAlo[0][0]);
    const uint32_t bBhi = (uint32_t)__cvta_generic_to_shared(&sBhi[0][0]);
    const uint32_t bBlo = (uint32_t)__cvta_generic_to_shared(&sBlo[0][0]);

    const int a_row = (lane & 15);
    const int a_k   = (lane >> 4) * 8;
    const int b_row = (lane & 7) + ((lane >> 4) << 3);
    const int b_k   = ((lane >> 3) & 1) * 8;

    for (int kc = 0; kc < 8; kc++) {
        const int k0 = kc * 32;
        #pragma unroll
        for (int h = 0; h < 2; h++) {
            int cc  = t + h * 256;
            int row = cc >> 2;
            int q   = cc & 3;
            size_t gA = (size_t)(m0 + row) * NH + k0 + q * 8;
            size_t gB = (size_t)(n0 + row) * NH + k0 + q * 8;
            *(uint4*)&sAhi[row][q * 8] = *(const uint4*)(g_Ahi + gA);
            *(uint4*)&sAlo[row][q * 8] = *(const uint4*)(g_Alo + gA);
            *(uint4*)&sBhi[row][q * 8] = *(const uint4*)(g_Whi + gB);
            *(uint4*)&sBlo[row][q * 8] = *(const uint4*)(g_Wlo + gB);
        }
        __syncthreads();

        #pragma unroll
        for (int ks = 0; ks < 32; ks += 16) {
            uint32_t af[4][4];
            uint32_t bh[4][2], bl[4][2];

            #pragma unroll
            for (int nh = 0; nh < 2; nh++) {
                int roff = (wn * 32 + nh * 16 + b_row) * 40 + ks + b_k;
                uint32_t r0, r1, r2, r3;
                LDM_A(r0, r1, r2, r3, bBhi + roff * 2);
                bh[2*nh][0] = r0; bh[2*nh][1] = r1;
                bh[2*nh+1][0] = r2; bh[2*nh+1][1] = r3;
                LDM_A(r0, r1, r2, r3, bBlo + roff * 2);
                bl[2*nh][0] = r0; bl[2*nh][1] = r1;
                bl[2*nh+1][0] = r2; bl[2*nh+1][1] = r3;
            }

            #pragma unroll
            for (int mi = 0; mi < 4; mi++) {
                int roff = (wm * 64 + mi * 16 + a_row) * 40 + ks + a_k;
                LDM_A(af[mi][0], af[mi][1], af[mi][2], af[mi][3], bAhi + roff * 2);
            }
            #pragma unroll
            for (int mi = 0; mi < 4; mi++)
                #pragma unroll
                for (int ni = 0; ni < 4; ni++) {
                    MMA_BF16(acc[mi][ni], af[mi], bh[ni]);
                    MMA_BF16(acc[mi][ni], af[mi], bl[ni]);
                }
            #pragma unroll
            for (int mi = 0; mi < 4; mi++) {
                int roff = (wm * 64 + mi * 16 + a_row) * 40 + ks + a_k;
                LDM_A(af[mi][0], af[mi][1], af[mi][2], af[mi][3], bAlo + roff * 2);
            }
            #pragma unroll
            for (int mi = 0; mi < 4; mi++)
                #pragma unroll
                for (int ni = 0; ni < 4; ni++)
                    MMA_BF16(acc[mi][ni], af[mi], bh[ni]);
        }
        __syncthreads();
    }

    const int g  = lane >> 2;
    const int t4 = lane & 3;
    #pragma unroll
    for (int mi = 0; mi < 4; mi++) {
        #pragma unroll
        for (int ni = 0; ni < 4; ni++) {
            int col = n0 + wn * 32 + ni * 8 + t4 * 2;
            if (col < NVOC) {
                float b0 = bias[col], b1 = bias[col + 1];
                int row0 = m0 + wm * 64 + mi * 16 + g;
                float2 v0 = make_float2(acc[mi][ni][0] + b0, acc[mi][ni][1] + b1);
                float2 v1 = make_float2(acc[mi][ni][2] + b0, acc[mi][ni][3] + b1);
                *(float2*)(out + (size_t)row0 * NVOC + col) = v0;
                *(float2*)(out + (size_t)(row0 + 8) * NVOC + col) = v1;
            }
        }
    }
}

// ---------------- launch ----------------
extern "C" void kernel_launch(void* const* d_in, const int* in_sizes, int n_in,
                              void* d_out, int out_size) {
    const int*   tokens  = (const int*)  d_in[0];
    const float* embed_W = (const float*)d_in[1];
    const float* Wx0     = (const float*)d_in[2];
    const float* Wh0     = (const float*)d_in[3];
    const float* b0      = (const float*)d_in[4];
    const float* Wx1     = (const float*)d_in[5];
    const float* Wh1     = (const float*)d_in[6];
    const float* b1      = (const float*)d_in[7];
    const float* dec_W   = (const float*)d_in[8];
    const float* dec_b   = (const float*)d_in[9];
    (void)in_sizes; (void)n_in;

    float* out    = (float*)d_out;
    float* h1_out = out + (size_t)out_size - 2 * BATCH * NH;
    float* h2_out = out + (size_t)out_size - 1 * BATCH * NH;

    static bool attr_done = false;
    if (!attr_done) {
        cudaFuncSetAttribute(fused_rnn, cudaFuncAttributeMaxDynamicSharedMemorySize, SMEM_BYTES);
        attr_done = true;
    }

    conv_W<<<(NVPAD * NH + 255) / 256, 256>>>(dec_W);
    init_state<<<16, 256>>>();
    gemm_gx<<<dim3(8, 64), 256>>>(embed_W, tokens, Wx0, b0);
    fused_rnn<<<128, 256, SMEM_BYTES>>>(Wh0, Wx1, Wh1, b1, h1_out, h2_out);
    gemm_dec_tc<<<dim3(79, 64), 256>>>(dec_b, out);
}